// round 15
// baseline (speedup 1.0000x reference)
#include <cuda_runtime.h>
#include <cuda_fp16.h>
#include <math_constants.h>

#define EPS 1e-5f
#define NMAX 100000
typedef unsigned int uint;

// Gather table: H2'[n][o] fp16, row = 64 halves = 128 B.
__device__ __half2 g_H2[(size_t)NMAX * 32];

#define PITCH 72   // smem row pitch in halves (144 B): conflict-free frag loads

// Prepacked weights (final smem layout) + bn constants.
__device__ __half g_w1T[64 * PITCH];   // [o][c] = w1[c][o]
__device__ __half g_w2T[64 * PITCH];   // [o][c] = conv_w[o][3+c]
__device__ __half g_w3T[64 * PITCH];   // [o][c] = w3[c][o]
// layout: s1 t1 wx wy wz s2 t2 s3 t3 (9 x 64 floats)
__device__ float  g_cst[9 * 64];

// mma.sync m16n8k16, fp16 inputs, fp32 accum (HMMA.16816 on sm_103a)
__device__ __forceinline__ void mma16816(float* c,
                                         uint a0, uint a1, uint a2, uint a3,
                                         uint b0, uint b1)
{
    asm volatile(
        "mma.sync.aligned.m16n8k16.row.col.f32.f16.f16.f32 "
        "{%0,%1,%2,%3}, {%4,%5,%6,%7}, {%8,%9}, {%0,%1,%2,%3};"
        : "+f"(c[0]), "+f"(c[1]), "+f"(c[2]), "+f"(c[3])
        : "r"(a0), "r"(a1), "r"(a2), "r"(a3), "r"(b0), "r"(b1));
}

// L2-only gather load (no L1 allocate): ld.global.cg.b32
__device__ __forceinline__ __half2 ldcg_h2(const void* ptr) {
    uint r;
    asm volatile("ld.global.cg.b32 %0, [%1];" : "=r"(r) : "l"(ptr));
    return *(__half2*)&r;
}

// ---------------------------------------------------------------------------
// Prep: 17 blocks x 256 threads, one element per thread (fully parallel).
// ---------------------------------------------------------------------------
__global__ __launch_bounds__(256) void prep_kernel(
    const float* __restrict__ w1, const float* __restrict__ conv_w,
    const float* __restrict__ w3,
    const float* __restrict__ g1, const float* __restrict__ b1,
    const float* __restrict__ m1, const float* __restrict__ v1,
    const float* __restrict__ g2, const float* __restrict__ b2,
    const float* __restrict__ m2, const float* __restrict__ v2,
    const float* __restrict__ g3, const float* __restrict__ b3,
    const float* __restrict__ m3, const float* __restrict__ v3)
{
    const int gt = blockIdx.x * 256 + threadIdx.x;   // 0 .. 4351
    if (gt < 4096) {
        int c = gt >> 6, o = gt & 63;
        g_w1T[o * PITCH + c] = __float2half(w1[gt]);
        g_w3T[o * PITCH + c] = __float2half(w3[gt]);
    }
    if (gt < 64 * 67) {
        int o = gt / 67, r = gt - o * 67;
        float v = conv_w[gt];
        if (r >= 3) g_w2T[o * PITCH + (r - 3)] = __float2half(v);
        else        g_cst[(2 + r) * 64 + o] = v;   // wx, wy, wz
    }
    if (gt < 64) {
        float s1 = g1[gt] * rsqrtf(v1[gt] + EPS);
        g_cst[0 * 64 + gt] = s1;
        g_cst[1 * 64 + gt] = b1[gt] - m1[gt] * s1;
        float s2 = g2[gt] * rsqrtf(v2[gt] + EPS);
        g_cst[5 * 64 + gt] = s2;
        g_cst[6 * 64 + gt] = b2[gt] - m2[gt] * s2;
        float s3 = g3[gt] * rsqrtf(v3[gt] + EPS);
        g_cst[7 * 64 + gt] = s3;
        g_cst[8 * 64 + gt] = b3[gt] - m3[gt] * s3;
    }
}

// ---------------------------------------------------------------------------
// Stage 1 (PDL secondary of prep): x load (input-only) -> grid-dep-sync ->
// prepacked weight copies -> GEMM1 -> bn1+relu -> GEMM2 -> +p.Wxyz -> g_H2.
// (R12/R14 verbatim.)
// ---------------------------------------------------------------------------
__global__ __launch_bounds__(256, 4) void stage1_kernel(
    const float* __restrict__ p, const float* __restrict__ x, int N)
{
    __shared__ __align__(16) __half xh[128 * PITCH];
    __shared__ __align__(16) __half w1T[64 * PITCH];
    __shared__ __align__(16) __half w2T[64 * PITCH];
    __shared__ __align__(16) float cst[5 * 64];   // s1 t1 wx wy wz

    const int tid = threadIdx.x;
    const int n0 = blockIdx.x * 128;

    // ---- input-only prologue (overlaps prep) ----
    const float4* xg = (const float4*)x;
#pragma unroll
    for (int it = 0; it < 8; it++) {
        int e = tid + it * 256;
        int pt = e >> 4, c4 = e & 15;
        int n = n0 + pt;
        float4 v = make_float4(0.f, 0.f, 0.f, 0.f);
        if (n < N) v = xg[(size_t)n * 16 + c4];
        __half2* d = (__half2*)&xh[pt * PITCH + c4 * 4];
        d[0] = __floats2half2_rn(v.x, v.y);
        d[1] = __floats2half2_rn(v.z, v.w);
    }

    cudaGridDependencySynchronize();   // prep outputs now visible

    {
        const uint4* s1g = (const uint4*)g_w1T;
        const uint4* s2g = (const uint4*)g_w2T;
        uint4* d1 = (uint4*)w1T;
        uint4* d2 = (uint4*)w2T;
#pragma unroll
        for (int it = 0; it < 3; it++) {
            int i = tid + it * 256;
            if (i < 576) { d1[i] = s1g[i]; d2[i] = s2g[i]; }
        }
        if (tid < 80) ((float4*)cst)[tid] = ((const float4*)g_cst)[tid];
    }
    __syncthreads();

    const float* s1s = cst;
    const float* t1s = cst + 64;
    const float* wxs = cst + 128;
    const float* wys = cst + 192;
    const float* wzs = cst + 256;

    const int w = tid >> 5, l = tid & 31;
    const int gr = l >> 2, q = l & 3;
    const int rA = w * 16 + gr;

    float acc[8][4];
#pragma unroll
    for (int nt = 0; nt < 8; nt++)
#pragma unroll
        for (int j = 0; j < 4; j++) acc[nt][j] = 0.f;

#pragma unroll
    for (int kt = 0; kt < 4; kt++) {
        int k0 = kt * 16 + 2 * q;
        uint a0 = *(const uint*)&xh[rA * PITCH + k0];
        uint a1 = *(const uint*)&xh[(rA + 8) * PITCH + k0];
        uint a2 = *(const uint*)&xh[rA * PITCH + k0 + 8];
        uint a3 = *(const uint*)&xh[(rA + 8) * PITCH + k0 + 8];
#pragma unroll
        for (int nt = 0; nt < 8; nt++) {
            uint b0 = *(const uint*)&w1T[(nt * 8 + gr) * PITCH + k0];
            uint b1 = *(const uint*)&w1T[(nt * 8 + gr) * PITCH + k0 + 8];
            mma16816(acc[nt], a0, a1, a2, a3, b0, b1);
        }
    }

#pragma unroll
    for (int nt = 0; nt < 8; nt++) {
        int c = nt * 8 + 2 * q;
        float2 sv = *(const float2*)&s1s[c];
        float2 tv = *(const float2*)&t1s[c];
        float h00 = fmaxf(fmaf(acc[nt][0], sv.x, tv.x), 0.f);
        float h01 = fmaxf(fmaf(acc[nt][1], sv.y, tv.y), 0.f);
        float h10 = fmaxf(fmaf(acc[nt][2], sv.x, tv.x), 0.f);
        float h11 = fmaxf(fmaf(acc[nt][3], sv.y, tv.y), 0.f);
        *(__half2*)&xh[rA * PITCH + c]       = __floats2half2_rn(h00, h01);
        *(__half2*)&xh[(rA + 8) * PITCH + c] = __floats2half2_rn(h10, h11);
#pragma unroll
        for (int j = 0; j < 4; j++) acc[nt][j] = 0.f;
    }
    __syncwarp();

#pragma unroll
    for (int kt = 0; kt < 4; kt++) {
        int k0 = kt * 16 + 2 * q;
        uint a0 = *(const uint*)&xh[rA * PITCH + k0];
        uint a1 = *(const uint*)&xh[(rA + 8) * PITCH + k0];
        uint a2 = *(const uint*)&xh[rA * PITCH + k0 + 8];
        uint a3 = *(const uint*)&xh[(rA + 8) * PITCH + k0 + 8];
#pragma unroll
        for (int nt = 0; nt < 8; nt++) {
            uint b0 = *(const uint*)&w2T[(nt * 8 + gr) * PITCH + k0];
            uint b1 = *(const uint*)&w2T[(nt * 8 + gr) * PITCH + k0 + 8];
            mma16816(acc[nt], a0, a1, a2, a3, b0, b1);
        }
    }
    __syncwarp();

    const int nA = n0 + rA, nB = nA + 8;
    float pxA = 0.f, pyA = 0.f, pzA = 0.f, pxB = 0.f, pyB = 0.f, pzB = 0.f;
    if (nA < N) { pxA = p[(size_t)nA * 3]; pyA = p[(size_t)nA * 3 + 1]; pzA = p[(size_t)nA * 3 + 2]; }
    if (nB < N) { pxB = p[(size_t)nB * 3]; pyB = p[(size_t)nB * 3 + 1]; pzB = p[(size_t)nB * 3 + 2]; }
#pragma unroll
    for (int nt = 0; nt < 8; nt++) {
        int c = nt * 8 + 2 * q;
        float wx0 = wxs[c], wx1 = wxs[c + 1];
        float wy0 = wys[c], wy1 = wys[c + 1];
        float wz0 = wzs[c], wz1 = wzs[c + 1];
        float v00 = acc[nt][0] + fmaf(pxA, wx0, fmaf(pyA, wy0, pzA * wz0));
        float v01 = acc[nt][1] + fmaf(pxA, wx1, fmaf(pyA, wy1, pzA * wz1));
        float v10 = acc[nt][2] + fmaf(pxB, wx0, fmaf(pyB, wy0, pzB * wz0));
        float v11 = acc[nt][3] + fmaf(pxB, wx1, fmaf(pyB, wy1, pzB * wz1));
        *(__half2*)&xh[rA * PITCH + c]       = __floats2half2_rn(v00, v01);
        *(__half2*)&xh[(rA + 8) * PITCH + c] = __floats2half2_rn(v10, v11);
    }
    __syncthreads();

#pragma unroll
    for (int it = 0; it < 4; it++) {
        int e = tid + it * 256;
        int row = e >> 3, seg = e & 7;
        int n = n0 + row;
        if (n < N)
            *(uint4*)((char*)g_H2 + (size_t)n * 128 + seg * 16) =
                *(const uint4*)&xh[row * PITCH + seg * 8];
    }
}

// ---------------------------------------------------------------------------
// Stage 2 (PDL secondary of stage1): block = 128 points, 512 threads
// (16 warps), 3 blocks/SM. Halves per-point w3T-copy overhead and grid size;
// Fsh zeroing only on the tail block. Phase A/B per-warp code as R12.
// ---------------------------------------------------------------------------
__global__ __launch_bounds__(512, 3) void stage2_kernel(
    const float* __restrict__ p, const float* __restrict__ x,
    const int* __restrict__ idx, float* __restrict__ out, int N)
{
    __shared__ __align__(16) __half Fsh[128 * PITCH];   // 18.4 KB
    __shared__ __align__(16) __half w3T[64 * PITCH];    // 9.2 KB
    __shared__ __align__(16) int idxs[2048];            // 8 KB
    __shared__ __align__(16) float cst[7 * 64];         // wx wy wz s2 t2 s3 t3
    __shared__ float ps[128 * 3];

    const int tid = threadIdx.x;
    const int n0 = blockIdx.x * 128;
    const int nblk = (N - n0 < 128) ? (N - n0) : 128;

    // ---- input-only prologue (overlaps stage1 tail) ----
    if (nblk < 128) {
        // tail block only: zero Fsh so mma sees 0 rows beyond nblk
#pragma unroll
        for (int it = 0; it < 3; it++) {
            int e = tid + it * 512;
            if (e < 128 * PITCH / 8) ((uint4*)Fsh)[e] = make_uint4(0u, 0u, 0u, 0u);
        }
    }
    if (tid < nblk * 4)
        *(int4*)&idxs[tid * 4] = ((const int4*)(idx + (size_t)n0 * 16))[tid];
    if (tid < nblk * 3)
        ps[tid] = p[(size_t)n0 * 3 + tid];

    cudaGridDependencySynchronize();   // stage1 (and transitively prep) done

    {
        const uint4* sg = (const uint4*)g_w3T;
        uint4* d = (uint4*)w3T;
#pragma unroll
        for (int it = 0; it < 2; it++) {
            int i = tid + it * 512;
            if (i < 576) d[i] = sg[i];
        }
        if (tid < 112) ((float4*)cst)[tid] = ((const float4*)(g_cst + 128))[tid];
    }
    __syncthreads();

    const float* wxs = cst;
    const float* wys = cst + 64;
    const float* wzs = cst + 128;
    const float* s2s = cst + 192;
    const float* t2s = cst + 256;
    const float* s3s = cst + 320;
    const float* t3s = cst + 384;

    const int w = tid >> 5;     // 0..15
    const int t = tid & 31;
    const int n0w = n0 + w * 8;

    // ---- Phase A: gather-max (2 x 8-load batches + tree hmax) ----
    if (n0w < N) {                         // N % 8 == 0: warp all-valid
        const int o0 = 2 * t;
        const int4* wib4 = (const int4*)&idxs[w * 128];
        const char* basep = (const char*)g_H2 + 4 * t;

        const float sb20 = s2s[o0], sb21 = s2s[o0 + 1];
        const float tb20 = t2s[o0], tb21 = t2s[o0 + 1];
        const float wx0 = wxs[o0], wx1 = wxs[o0 + 1];
        const float wy0 = wys[o0], wy1 = wys[o0 + 1];
        const float wz0 = wzs[o0], wz1 = wzs[o0 + 1];
#pragma unroll
        for (int pt = 0; pt < 8; pt++) {
            int4 ia = wib4[pt * 4 + 0];
            int4 ib = wib4[pt * 4 + 1];
            __half2 v0 = ldcg_h2(basep + ((size_t)((uint)ia.x << 7)));
            __half2 v1 = ldcg_h2(basep + ((size_t)((uint)ia.y << 7)));
            __half2 v2_ = ldcg_h2(basep + ((size_t)((uint)ia.z << 7)));
            __half2 v3_ = ldcg_h2(basep + ((size_t)((uint)ia.w << 7)));
            __half2 v4 = ldcg_h2(basep + ((size_t)((uint)ib.x << 7)));
            __half2 v5 = ldcg_h2(basep + ((size_t)((uint)ib.y << 7)));
            __half2 v6 = ldcg_h2(basep + ((size_t)((uint)ib.z << 7)));
            __half2 v7 = ldcg_h2(basep + ((size_t)((uint)ib.w << 7)));
            v0 = __hmax2(v0, v1); v2_ = __hmax2(v2_, v3_);
            v4 = __hmax2(v4, v5); v6 = __hmax2(v6, v7);
            v0 = __hmax2(v0, v2_); v4 = __hmax2(v4, v6);
            __half2 m1st = __hmax2(v0, v4);

            int4 ic = wib4[pt * 4 + 2];
            int4 id = wib4[pt * 4 + 3];
            v0 = ldcg_h2(basep + ((size_t)((uint)ic.x << 7)));
            v1 = ldcg_h2(basep + ((size_t)((uint)ic.y << 7)));
            v2_ = ldcg_h2(basep + ((size_t)((uint)ic.z << 7)));
            v3_ = ldcg_h2(basep + ((size_t)((uint)ic.w << 7)));
            v4 = ldcg_h2(basep + ((size_t)((uint)id.x << 7)));
            v5 = ldcg_h2(basep + ((size_t)((uint)id.y << 7)));
            v6 = ldcg_h2(basep + ((size_t)((uint)id.z << 7)));
            v7 = ldcg_h2(basep + ((size_t)((uint)id.w << 7)));
            v0 = __hmax2(v0, v1); v2_ = __hmax2(v2_, v3_);
            v4 = __hmax2(v4, v5); v6 = __hmax2(v6, v7);
            v0 = __hmax2(v0, v2_); v4 = __hmax2(v4, v6);
            v0 = __hmax2(v0, v4);
            v0 = __hmax2(v0, m1st);

            const float* pr = &ps[(w * 8 + pt) * 3];
            float px = pr[0], py = pr[1], pz = pr[2];
            float c0 = fmaf(px, wx0, fmaf(py, wy0, pz * wz0));
            float c1 = fmaf(px, wx1, fmaf(py, wy1, pz * wz1));

            float2 mf = __half22float2(v0);
            float f0 = fmaxf(fmaf(mf.x - c0, sb20, tb20), 0.f);
            float f1 = fmaxf(fmaf(mf.y - c1, sb21, tb21), 0.f);
            *(__half2*)&Fsh[(w * 8 + pt) * PITCH + o0] = __floats2half2_rn(f0, f1);
        }
    }
    __syncthreads();

    // ---- Phase B: C = F @ w3 via mma; warp = m-tile (w&7), n-half (w>>3) ----
    const int gr = t >> 2, q = t & 3;
    const int mt = w & 7, nh = w >> 3;
    const int rA = mt * 16 + gr;

    float acc[4][4];
#pragma unroll
    for (int j = 0; j < 4; j++)
#pragma unroll
        for (int i = 0; i < 4; i++) acc[j][i] = 0.f;

#pragma unroll
    for (int kt = 0; kt < 4; kt++) {
        int k0 = kt * 16 + 2 * q;
        uint a0 = *(const uint*)&Fsh[rA * PITCH + k0];
        uint a1 = *(const uint*)&Fsh[(rA + 8) * PITCH + k0];
        uint a2 = *(const uint*)&Fsh[rA * PITCH + k0 + 8];
        uint a3 = *(const uint*)&Fsh[(rA + 8) * PITCH + k0 + 8];
#pragma unroll
        for (int j = 0; j < 4; j++) {
            int nr = (nh * 4 + j) * 8 + gr;
            uint b0 = *(const uint*)&w3T[nr * PITCH + k0];
            uint b1 = *(const uint*)&w3T[nr * PITCH + k0 + 8];
            mma16816(acc[j], a0, a1, a2, a3, b0, b1);
        }
    }

    // ---- epilogue: bn3 + residual + relu (streaming) ----
    const int nA = n0 + rA, nB = nA + 8;
#pragma unroll
    for (int j = 0; j < 4; j++) {
        int c = (nh * 4 + j) * 8 + 2 * q;
        float2 sv = *(const float2*)&s3s[c];
        float2 tv = *(const float2*)&t3s[c];
        if (nA < N) {
            float2 xv = __ldcs((const float2*)&x[(size_t)nA * 64 + c]);
            float r0 = fmaxf(fmaf(acc[j][0], sv.x, tv.x) + xv.x, 0.f);
            float r1 = fmaxf(fmaf(acc[j][1], sv.y, tv.y) + xv.y, 0.f);
            __stcs((float2*)&out[(size_t)nA * 64 + c], make_float2(r0, r1));
        }
        if (nB < N) {
            float2 xv = __ldcs((const float2*)&x[(size_t)nB * 64 + c]);
            float r0 = fmaxf(fmaf(acc[j][2], sv.x, tv.x) + xv.x, 0.f);
            float r1 = fmaxf(fmaf(acc[j][3], sv.y, tv.y) + xv.y, 0.f);
            __stcs((float2*)&out[(size_t)nB * 64 + c], make_float2(r0, r1));
        }
    }
}

extern "C" void kernel_launch(void* const* d_in, const int* in_sizes, int n_in,
                              void* d_out, int out_size)
{
    const float* p      = (const float*)d_in[0];
    const float* x      = (const float*)d_in[1];
    const int*   idx    = (const int*)  d_in[2];
    const float* w1     = (const float*)d_in[3];
    const float* g1     = (const float*)d_in[4];
    const float* b1     = (const float*)d_in[5];
    const float* m1     = (const float*)d_in[6];
    const float* v1     = (const float*)d_in[7];
    const float* conv_w = (const float*)d_in[8];
    const float* g2     = (const float*)d_in[9];
    const float* b2     = (const float*)d_in[10];
    const float* m2     = (const float*)d_in[11];
    const float* v2     = (const float*)d_in[12];
    const float* w3     = (const float*)d_in[13];
    const float* g3     = (const float*)d_in[14];
    const float* b3     = (const float*)d_in[15];
    const float* m3     = (const float*)d_in[16];
    const float* v3     = (const float*)d_in[17];
    float* out = (float*)d_out;

    const int N = in_sizes[0] / 3;

    prep_kernel<<<17, 256>>>(w1, conv_w, w3,
                             g1, b1, m1, v1, g2, b2, m2, v2, g3, b3, m3, v3);

    cudaLaunchAttribute pdl[1];
    pdl[0].id = cudaLaunchAttributeProgrammaticStreamSerialization;
    pdl[0].val.programmaticStreamSerializationAllowed = 1;

    {
        cudaLaunchConfig_t cfg = {};
        cfg.gridDim = dim3((N + 127) / 128);
        cfg.blockDim = dim3(256);
        cfg.attrs = pdl;
        cfg.numAttrs = 1;
        cudaLaunchKernelEx(&cfg, stage1_kernel, p, x, N);
    }
    {
        cudaLaunchConfig_t cfg = {};
        cfg.gridDim = dim3((N + 127) / 128);
        cfg.blockDim = dim3(512);
        cfg.attrs = pdl;
        cfg.numAttrs = 1;
        cudaLaunchKernelEx(&cfg, stage2_kernel, p, x, idx, out, N);
    }
}

// round 17
// speedup vs baseline: 1.0479x; 1.0479x over previous
#include <cuda_runtime.h>
#include <cuda_fp16.h>
#include <math_constants.h>

#define EPS 1e-5f
#define NMAX 100000
typedef unsigned int uint;

// Gather table: H2'[n][o] fp16, row = 64 halves = 128 B.
__device__ __half2 g_H2[(size_t)NMAX * 32];

#define PITCH 72   // smem row pitch in halves (144 B): conflict-free frag loads

// Prepacked weights (final smem layout) + bn constants.
__device__ __half g_w1T[64 * PITCH];   // [o][c] = w1[c][o]
__device__ __half g_w2T[64 * PITCH];   // [o][c] = conv_w[o][3+c]
__device__ __half g_w3T[64 * PITCH];   // [o][c] = w3[c][o]
// layout: s1 t1 wx wy wz s2 t2 s3 t3 (9 x 64 floats)
__device__ float  g_cst[9 * 64];

// mma.sync m16n8k16, fp16 inputs, fp32 accum (HMMA.16816 on sm_103a)
__device__ __forceinline__ void mma16816(float* c,
                                         uint a0, uint a1, uint a2, uint a3,
                                         uint b0, uint b1)
{
    asm volatile(
        "mma.sync.aligned.m16n8k16.row.col.f32.f16.f16.f32 "
        "{%0,%1,%2,%3}, {%4,%5,%6,%7}, {%8,%9}, {%0,%1,%2,%3};"
        : "+f"(c[0]), "+f"(c[1]), "+f"(c[2]), "+f"(c[3])
        : "r"(a0), "r"(a1), "r"(a2), "r"(a3), "r"(b0), "r"(b1));
}

// ldmatrix x4 (non-trans): 4 m8n8 b16 tiles, per-lane row address.
__device__ __forceinline__ void ldsm_x4(uint addr, uint& r0, uint& r1,
                                        uint& r2, uint& r3)
{
    asm volatile("ldmatrix.sync.aligned.m8n8.x4.shared.b16 {%0,%1,%2,%3}, [%4];"
                 : "=r"(r0), "=r"(r1), "=r"(r2), "=r"(r3) : "r"(addr));
}

// L2-only gather load (no L1 allocate): ld.global.cg.b32
__device__ __forceinline__ __half2 ldcg_h2(const void* ptr) {
    uint r;
    asm volatile("ld.global.cg.b32 %0, [%1];" : "=r"(r) : "l"(ptr));
    return *(__half2*)&r;
}

// ---------------------------------------------------------------------------
// Prep: 17 blocks x 256 threads, one element per thread (fully parallel).
// ---------------------------------------------------------------------------
__global__ __launch_bounds__(256) void prep_kernel(
    const float* __restrict__ w1, const float* __restrict__ conv_w,
    const float* __restrict__ w3,
    const float* __restrict__ g1, const float* __restrict__ b1,
    const float* __restrict__ m1, const float* __restrict__ v1,
    const float* __restrict__ g2, const float* __restrict__ b2,
    const float* __restrict__ m2, const float* __restrict__ v2,
    const float* __restrict__ g3, const float* __restrict__ b3,
    const float* __restrict__ m3, const float* __restrict__ v3)
{
    const int gt = blockIdx.x * 256 + threadIdx.x;   // 0 .. 4351
    if (gt < 4096) {
        int c = gt >> 6, o = gt & 63;
        g_w1T[o * PITCH + c] = __float2half(w1[gt]);
        g_w3T[o * PITCH + c] = __float2half(w3[gt]);
    }
    if (gt < 64 * 67) {
        int o = gt / 67, r = gt - o * 67;
        float v = conv_w[gt];
        if (r >= 3) g_w2T[o * PITCH + (r - 3)] = __float2half(v);
        else        g_cst[(2 + r) * 64 + o] = v;   // wx, wy, wz
    }
    if (gt < 64) {
        float s1 = g1[gt] * rsqrtf(v1[gt] + EPS);
        g_cst[0 * 64 + gt] = s1;
        g_cst[1 * 64 + gt] = b1[gt] - m1[gt] * s1;
        float s2 = g2[gt] * rsqrtf(v2[gt] + EPS);
        g_cst[5 * 64 + gt] = s2;
        g_cst[6 * 64 + gt] = b2[gt] - m2[gt] * s2;
        float s3 = g3[gt] * rsqrtf(v3[gt] + EPS);
        g_cst[7 * 64 + gt] = s3;
        g_cst[8 * 64 + gt] = b3[gt] - m3[gt] * s3;
    }
}

// ---------------------------------------------------------------------------
// Stage 1 (PDL secondary of prep): x load (input-only) -> grid-dep-sync ->
// prepacked weight copies -> GEMM1 -> bn1+relu -> GEMM2 -> +p.Wxyz -> g_H2.
// Fragment loads via ldmatrix.x4 (A: 1/kt, B: 4/kt).
// ---------------------------------------------------------------------------
__global__ __launch_bounds__(256, 4) void stage1_kernel(
    const float* __restrict__ p, const float* __restrict__ x, int N)
{
    __shared__ __align__(16) __half xh[128 * PITCH];
    __shared__ __align__(16) __half w1T[64 * PITCH];
    __shared__ __align__(16) __half w2T[64 * PITCH];
    __shared__ __align__(16) float cst[5 * 64];   // s1 t1 wx wy wz

    const int tid = threadIdx.x;
    const int n0 = blockIdx.x * 128;

    // ---- input-only prologue (overlaps prep) ----
    const float4* xg = (const float4*)x;
#pragma unroll
    for (int it = 0; it < 8; it++) {
        int e = tid + it * 256;
        int pt = e >> 4, c4 = e & 15;
        int n = n0 + pt;
        float4 v = make_float4(0.f, 0.f, 0.f, 0.f);
        if (n < N) v = xg[(size_t)n * 16 + c4];
        __half2* d = (__half2*)&xh[pt * PITCH + c4 * 4];
        d[0] = __floats2half2_rn(v.x, v.y);
        d[1] = __floats2half2_rn(v.z, v.w);
    }

    cudaGridDependencySynchronize();   // prep outputs now visible

    {
        const uint4* s1g = (const uint4*)g_w1T;
        const uint4* s2g = (const uint4*)g_w2T;
        uint4* d1 = (uint4*)w1T;
        uint4* d2 = (uint4*)w2T;
#pragma unroll
        for (int it = 0; it < 3; it++) {
            int i = tid + it * 256;
            if (i < 576) { d1[i] = s1g[i]; d2[i] = s2g[i]; }
        }
        if (tid < 80) ((float4*)cst)[tid] = ((const float4*)g_cst)[tid];
    }
    __syncthreads();

    const float* s1s = cst;
    const float* t1s = cst + 64;
    const float* wxs = cst + 128;
    const float* wys = cst + 192;
    const float* wzs = cst + 256;

    const int w = tid >> 5, l = tid & 31;
    const int gr = l >> 2, q = l & 3;
    const int rA = w * 16 + gr;

    // ldmatrix per-lane row addresses.
    // A tiles: T0 rows+0 k+0 | T1 rows+8 k+0 | T2 rows+0 k+8 | T3 rows+8 k+8
    const int ltile = l >> 3, lrow = l & 7;
    const uint a_row = (uint)(w * 16 + (ltile & 1) * 8 + lrow);
    const uint a_koff = (uint)((ltile >> 1) * 8);
    const uint xh_base = (uint)__cvta_generic_to_shared(xh);
    const uint a_addr0 = xh_base + (a_row * PITCH + a_koff) * 2;
    // B tiles for pair pn (nt0=2pn, nt1=2pn+1):
    //   T0 rows nt0*8.. k+0 | T1 k+8 | T2 rows nt1*8.. k+0 | T3 k+8
    const uint b_row_off = (uint)((ltile & 1) ? 8 : 0);   // within-pair nt select
    const uint b_koff = (uint)((ltile & 2) ? 8 : 0);
    // NOTE tile order must be T0=(nt0,k0) T1=(nt0,k8) T2=(nt1,k0) T3=(nt1,k8):
    //   r0=b0(nt0) r1=b1(nt0) r2=b0(nt1) r3=b1(nt1)
    const uint b_row_sel = (uint)((ltile >> 1) ? 8 : 0); // T2/T3 -> nt1
    const uint b_k_sel   = (uint)((ltile & 1) ? 8 : 0);  // T1/T3 -> k+8
    const uint w1_base = (uint)__cvta_generic_to_shared(w1T);
    const uint w2_base = (uint)__cvta_generic_to_shared(w2T);
    (void)b_row_off; (void)b_koff;

    float acc[8][4];
#pragma unroll
    for (int nt = 0; nt < 8; nt++)
#pragma unroll
        for (int j = 0; j < 4; j++) acc[nt][j] = 0.f;

    // ---- GEMM1 ----
#pragma unroll
    for (int kt = 0; kt < 4; kt++) {
        uint a0, a1, a2, a3;
        ldsm_x4(a_addr0 + kt * 32, a0, a1, a2, a3);
#pragma unroll
        for (int pn = 0; pn < 4; pn++) {
            uint r0, r1, r2, r3;
            uint brow = (uint)((2 * pn) * 8) + b_row_sel + lrow;
            ldsm_x4(w1_base + (brow * PITCH + b_k_sel) * 2 + kt * 32,
                    r0, r1, r2, r3);
            mma16816(acc[2 * pn + 0], a0, a1, a2, a3, r0, r1);
            mma16816(acc[2 * pn + 1], a0, a1, a2, a3, r2, r3);
        }
    }

    // ---- bn1 + relu -> h back into xh (own rows) ----
#pragma unroll
    for (int nt = 0; nt < 8; nt++) {
        int c = nt * 8 + 2 * q;
        float2 sv = *(const float2*)&s1s[c];
        float2 tv = *(const float2*)&t1s[c];
        float h00 = fmaxf(fmaf(acc[nt][0], sv.x, tv.x), 0.f);
        float h01 = fmaxf(fmaf(acc[nt][1], sv.y, tv.y), 0.f);
        float h10 = fmaxf(fmaf(acc[nt][2], sv.x, tv.x), 0.f);
        float h11 = fmaxf(fmaf(acc[nt][3], sv.y, tv.y), 0.f);
        *(__half2*)&xh[rA * PITCH + c]       = __floats2half2_rn(h00, h01);
        *(__half2*)&xh[(rA + 8) * PITCH + c] = __floats2half2_rn(h10, h11);
#pragma unroll
        for (int j = 0; j < 4; j++) acc[nt][j] = 0.f;
    }
    __syncwarp();

    // ---- GEMM2 ----
#pragma unroll
    for (int kt = 0; kt < 4; kt++) {
        uint a0, a1, a2, a3;
        ldsm_x4(a_addr0 + kt * 32, a0, a1, a2, a3);
#pragma unroll
        for (int pn = 0; pn < 4; pn++) {
            uint r0, r1, r2, r3;
            uint brow = (uint)((2 * pn) * 8) + b_row_sel + lrow;
            ldsm_x4(w2_base + (brow * PITCH + b_k_sel) * 2 + kt * 32,
                    r0, r1, r2, r3);
            mma16816(acc[2 * pn + 0], a0, a1, a2, a3, r0, r1);
            mma16816(acc[2 * pn + 1], a0, a1, a2, a3, r2, r3);
        }
    }
    __syncwarp();

    const int nA = n0 + rA, nB = nA + 8;
    float pxA = 0.f, pyA = 0.f, pzA = 0.f, pxB = 0.f, pyB = 0.f, pzB = 0.f;
    if (nA < N) { pxA = p[(size_t)nA * 3]; pyA = p[(size_t)nA * 3 + 1]; pzA = p[(size_t)nA * 3 + 2]; }
    if (nB < N) { pxB = p[(size_t)nB * 3]; pyB = p[(size_t)nB * 3 + 1]; pzB = p[(size_t)nB * 3 + 2]; }
#pragma unroll
    for (int nt = 0; nt < 8; nt++) {
        int c = nt * 8 + 2 * q;
        float wx0 = wxs[c], wx1 = wxs[c + 1];
        float wy0 = wys[c], wy1 = wys[c + 1];
        float wz0 = wzs[c], wz1 = wzs[c + 1];
        float v00 = acc[nt][0] + fmaf(pxA, wx0, fmaf(pyA, wy0, pzA * wz0));
        float v01 = acc[nt][1] + fmaf(pxA, wx1, fmaf(pyA, wy1, pzA * wz1));
        float v10 = acc[nt][2] + fmaf(pxB, wx0, fmaf(pyB, wy0, pzB * wz0));
        float v11 = acc[nt][3] + fmaf(pxB, wx1, fmaf(pyB, wy1, pzB * wz1));
        *(__half2*)&xh[rA * PITCH + c]       = __floats2half2_rn(v00, v01);
        *(__half2*)&xh[(rA + 8) * PITCH + c] = __floats2half2_rn(v10, v11);
    }
    __syncthreads();

#pragma unroll
    for (int it = 0; it < 4; it++) {
        int e = tid + it * 256;
        int row = e >> 3, seg = e & 7;
        int n = n0 + row;
        if (n < N)
            *(uint4*)((char*)g_H2 + (size_t)n * 128 + seg * 16) =
                *(const uint4*)&xh[row * PITCH + seg * 8];
    }
}

// ---------------------------------------------------------------------------
// Stage 2 (PDL secondary of stage1): R12 structure; phase B frag loads via
// ldmatrix (A: 1/kt, B: 2/kt).
// ---------------------------------------------------------------------------
__global__ __launch_bounds__(256, 6) void stage2_kernel(
    const float* __restrict__ p, const float* __restrict__ x,
    const int* __restrict__ idx, float* __restrict__ out, int N)
{
    __shared__ __align__(16) __half Fsh[64 * PITCH];
    __shared__ __align__(16) __half w3T[64 * PITCH];
    __shared__ __align__(16) int idxs[1024];
    __shared__ __align__(16) float cst[7 * 64];   // wx wy wz s2 t2 s3 t3
    __shared__ float ps[64 * 3];

    const int tid = threadIdx.x;
    const int n0 = blockIdx.x * 64;
    const int nblk = (N - n0 < 64) ? (N - n0) : 64;

    // ---- input-only prologue (overlaps stage1 tail) ----
#pragma unroll
    for (int it = 0; it < 3; it++) {
        int e = tid + it * 256;
        if (e < 64 * PITCH / 8) ((uint4*)Fsh)[e] = make_uint4(0u, 0u, 0u, 0u);
    }
    if (tid < nblk * 4)
        *(int4*)&idxs[tid * 4] = ((const int4*)(idx + (size_t)n0 * 16))[tid];
    if (tid < nblk * 3)
        ps[tid] = p[(size_t)n0 * 3 + tid];

    cudaGridDependencySynchronize();   // stage1 (and transitively prep) done

    {
        const uint4* sg = (const uint4*)g_w3T;
        uint4* d = (uint4*)w3T;
#pragma unroll
        for (int it = 0; it < 3; it++) {
            int i = tid + it * 256;
            if (i < 576) d[i] = sg[i];
        }
        if (tid < 112) ((float4*)cst)[tid] = ((const float4*)(g_cst + 128))[tid];
    }
    __syncthreads();

    const float* wxs = cst;
    const float* wys = cst + 64;
    const float* wzs = cst + 128;
    const float* s2s = cst + 192;
    const float* t2s = cst + 256;
    const float* s3s = cst + 320;
    const float* t3s = cst + 384;

    const int w = tid >> 5;
    const int t = tid & 31;
    const int n0w = n0 + w * 8;

    // ---- Phase A: gather-max (2 x 8-load batches + tree hmax) ----
    if (n0w < N) {                         // N % 8 == 0: warp all-valid
        const int o0 = 2 * t;
        const int4* wib4 = (const int4*)&idxs[w * 128];
        const char* basep = (const char*)g_H2 + 4 * t;

        const float sb20 = s2s[o0], sb21 = s2s[o0 + 1];
        const float tb20 = t2s[o0], tb21 = t2s[o0 + 1];
        const float wx0 = wxs[o0], wx1 = wxs[o0 + 1];
        const float wy0 = wys[o0], wy1 = wys[o0 + 1];
        const float wz0 = wzs[o0], wz1 = wzs[o0 + 1];
#pragma unroll
        for (int pt = 0; pt < 8; pt++) {
            int4 ia = wib4[pt * 4 + 0];
            int4 ib = wib4[pt * 4 + 1];
            __half2 v0 = ldcg_h2(basep + ((size_t)((uint)ia.x << 7)));
            __half2 v1 = ldcg_h2(basep + ((size_t)((uint)ia.y << 7)));
            __half2 v2_ = ldcg_h2(basep + ((size_t)((uint)ia.z << 7)));
            __half2 v3_ = ldcg_h2(basep + ((size_t)((uint)ia.w << 7)));
            __half2 v4 = ldcg_h2(basep + ((size_t)((uint)ib.x << 7)));
            __half2 v5 = ldcg_h2(basep + ((size_t)((uint)ib.y << 7)));
            __half2 v6 = ldcg_h2(basep + ((size_t)((uint)ib.z << 7)));
            __half2 v7 = ldcg_h2(basep + ((size_t)((uint)ib.w << 7)));
            v0 = __hmax2(v0, v1); v2_ = __hmax2(v2_, v3_);
            v4 = __hmax2(v4, v5); v6 = __hmax2(v6, v7);
            v0 = __hmax2(v0, v2_); v4 = __hmax2(v4, v6);
            __half2 m1st = __hmax2(v0, v4);

            int4 ic = wib4[pt * 4 + 2];
            int4 id = wib4[pt * 4 + 3];
            v0 = ldcg_h2(basep + ((size_t)((uint)ic.x << 7)));
            v1 = ldcg_h2(basep + ((size_t)((uint)ic.y << 7)));
            v2_ = ldcg_h2(basep + ((size_t)((uint)ic.z << 7)));
            v3_ = ldcg_h2(basep + ((size_t)((uint)ic.w << 7)));
            v4 = ldcg_h2(basep + ((size_t)((uint)id.x << 7)));
            v5 = ldcg_h2(basep + ((size_t)((uint)id.y << 7)));
            v6 = ldcg_h2(basep + ((size_t)((uint)id.z << 7)));
            v7 = ldcg_h2(basep + ((size_t)((uint)id.w << 7)));
            v0 = __hmax2(v0, v1); v2_ = __hmax2(v2_, v3_);
            v4 = __hmax2(v4, v5); v6 = __hmax2(v6, v7);
            v0 = __hmax2(v0, v2_); v4 = __hmax2(v4, v6);
            v0 = __hmax2(v0, v4);
            v0 = __hmax2(v0, m1st);

            const float* pr = &ps[(w * 8 + pt) * 3];
            float px = pr[0], py = pr[1], pz = pr[2];
            float c0 = fmaf(px, wx0, fmaf(py, wy0, pz * wz0));
            float c1 = fmaf(px, wx1, fmaf(py, wy1, pz * wz1));

            float2 mf = __half22float2(v0);
            float f0 = fmaxf(fmaf(mf.x - c0, sb20, tb20), 0.f);
            float f1 = fmaxf(fmaf(mf.y - c1, sb21, tb21), 0.f);
            *(__half2*)&Fsh[(w * 8 + pt) * PITCH + o0] = __floats2half2_rn(f0, f1);
        }
    }
    __syncthreads();

    // ---- Phase B: C = F @ w3 via mma; warp = m-tile (w&3), n-half (w>>2) ----
    const int gr = t >> 2, q = t & 3;
    const int mt = w & 3, nh = w >> 2;
    const int rA = mt * 16 + gr;
    (void)gr; (void)rA;

    const int ltile = t >> 3, lrow = t & 7;
    const uint a_row = (uint)(mt * 16 + (ltile & 1) * 8 + lrow);
    const uint a_koff = (uint)((ltile >> 1) * 8);
    const uint fsh_base = (uint)__cvta_generic_to_shared(Fsh);
    const uint a_addr0 = fsh_base + (a_row * PITCH + a_koff) * 2;
    const uint b_row_sel = (uint)((ltile >> 1) ? 8 : 0);
    const uint b_k_sel   = (uint)((ltile & 1) ? 8 : 0);
    const uint w3_base = (uint)__cvta_generic_to_shared(w3T);

    float acc[4][4];
#pragma unroll
    for (int j = 0; j < 4; j++)
#pragma unroll
        for (int i = 0; i < 4; i++) acc[j][i] = 0.f;

#pragma unroll
    for (int kt = 0; kt < 4; kt++) {
        uint a0, a1, a2, a3;
        ldsm_x4(a_addr0 + kt * 32, a0, a1, a2, a3);
#pragma unroll
        for (int pn = 0; pn < 2; pn++) {
            uint r0, r1, r2, r3;
            uint brow = (uint)((nh * 4 + 2 * pn) * 8) + b_row_sel + lrow;
            ldsm_x4(w3_base + (brow * PITCH + b_k_sel) * 2 + kt * 32,
                    r0, r1, r2, r3);
            mma16816(acc[2 * pn + 0], a0, a1, a2, a3, r0, r1);
            mma16816(acc[2 * pn + 1], a0, a1, a2, a3, r2, r3);
        }
    }

    // ---- epilogue: bn3 + residual + relu (streaming) ----
    const int nA = n0 + mt * 16 + (t >> 2), nB = nA + 8;
#pragma unroll
    for (int j = 0; j < 4; j++) {
        int c = (nh * 4 + j) * 8 + 2 * q;
        float2 sv = *(const float2*)&s3s[c];
        float2 tv = *(const float2*)&t3s[c];
        if (nA < N) {
            float2 xv = __ldcs((const float2*)&x[(size_t)nA * 64 + c]);
            float r0 = fmaxf(fmaf(acc[j][0], sv.x, tv.x) + xv.x, 0.f);
            float r1 = fmaxf(fmaf(acc[j][1], sv.y, tv.y) + xv.y, 0.f);
            __stcs((float2*)&out[(size_t)nA * 64 + c], make_float2(r0, r1));
        }
        if (nB < N) {
            float2 xv = __ldcs((const float2*)&x[(size_t)nB * 64 + c]);
            float r0 = fmaxf(fmaf(acc[j][2], sv.x, tv.x) + xv.x, 0.f);
            float r1 = fmaxf(fmaf(acc[j][3], sv.y, tv.y) + xv.y, 0.f);
            __stcs((float2*)&out[(size_t)nB * 64 + c], make_float2(r0, r1));
        }
    }
}

extern "C" void kernel_launch(void* const* d_in, const int* in_sizes, int n_in,
                              void* d_out, int out_size)
{
    const float* p      = (const float*)d_in[0];
    const float* x      = (const float*)d_in[1];
    const int*   idx    = (const int*)  d_in[2];
    const float* w1     = (const float*)d_in[3];
    const float* g1     = (const float*)d_in[4];
    const float* b1     = (const float*)d_in[5];
    const float* m1     = (const float*)d_in[6];
    const float* v1     = (const float*)d_in[7];
    const float* conv_w = (const float*)d_in[8];
    const float* g2     = (const float*)d_in[9];
    const float* b2     = (const float*)d_in[10];
    const float* m2     = (const float*)d_in[11];
    const float* v2     = (const float*)d_in[12];
    const float* w3     = (const float*)d_in[13];
    const float* g3     = (const float*)d_in[14];
    const float* b3     = (const float*)d_in[15];
    const float* m3     = (const float*)d_in[16];
    const float* v3     = (const float*)d_in[17];
    float* out = (float*)d_out;

    const int N = in_sizes[0] / 3;

    prep_kernel<<<17, 256>>>(w1, conv_w, w3,
                             g1, b1, m1, v1, g2, b2, m2, v2, g3, b3, m3, v3);

    cudaLaunchAttribute pdl[1];
    pdl[0].id = cudaLaunchAttributeProgrammaticStreamSerialization;
    pdl[0].val.programmaticStreamSerializationAllowed = 1;

    {
        cudaLaunchConfig_t cfg = {};
        cfg.gridDim = dim3((N + 127) / 128);
        cfg.blockDim = dim3(256);
        cfg.attrs = pdl;
        cfg.numAttrs = 1;
        cudaLaunchKernelEx(&cfg, stage1_kernel, p, x, N);
    }
    {
        cudaLaunchConfig_t cfg = {};
        cfg.gridDim = dim3((N + 63) / 64);
        cfg.blockDim = dim3(256);
        cfg.attrs = pdl;
        cfg.numAttrs = 1;
        cudaLaunchKernelEx(&cfg, stage2_kernel, p, x, idx, out, N);
    }
}